// round 5
// baseline (speedup 1.0000x reference)
#include <cuda_runtime.h>
#include <cuda_bf16.h>
#include <cstdint>

#define D        64
#define K        1024
#define NVEC     65536
#define QELEMS   (NVEC * D)
#define MTILE    128
#define NCHUNK   64
#define NCHUNKS  (K / NCHUNK)     // 16
#define GRID     (NVEC / MTILE)   // 512
#define EPS      0.02f

// smem offsets
#define OFF_A    0            // 128 rows x 256B (h|m, swizzled) = 32768
#define OFF_B    32768        // 2 stages x 32768 (B1 16K + B2 16K)
#define OFF_SN   98304        // 1024 floats = 4096
#define OFF_IDX  102400       // 128 ints
#define OFF_FLG  102912       // 128 ints
#define SMEM_SZ  103424

__device__ __nv_bfloat16 g_B1[K * 128];      // per codeword: [h | h]
__device__ __nv_bfloat16 g_B2[K * 128];      // per codeword: [m | m]
__device__ float g_enorm2[K];
__device__ int   g_flag_list[NVEC];
__device__ int   g_flag_count;

// ---------- helpers ----------
__device__ __forceinline__ uint32_t smem_u32(const void* p) {
    uint32_t a;
    asm("{ .reg .u64 t; cvta.to.shared.u64 t, %1; cvt.u32.u64 %0, t; }" : "=r"(a) : "l"(p));
    return a;
}
__device__ __forceinline__ void cp16(uint32_t dst, const void* src) {
    asm volatile("cp.async.cg.shared.global [%0], [%1], 16;" :: "r"(dst), "l"(src));
}
__device__ __forceinline__ void cp_commit() { asm volatile("cp.async.commit_group;" ::: "memory"); }
template<int N> __device__ __forceinline__ void cp_wait() {
    asm volatile("cp.async.wait_group %0;" :: "n"(N) : "memory");
}
__device__ __forceinline__ void ldsm4(uint32_t* r, uint32_t addr) {
    asm volatile("ldmatrix.sync.aligned.m8n8.x4.shared.b16 {%0,%1,%2,%3}, [%4];"
                 : "=r"(r[0]), "=r"(r[1]), "=r"(r[2]), "=r"(r[3]) : "r"(addr));
}
__device__ __forceinline__ void mma16816(float* c, const uint32_t* a, uint32_t b0, uint32_t b1) {
    asm volatile(
        "mma.sync.aligned.m16n8k16.row.col.f32.bf16.bf16.f32 "
        "{%0,%1,%2,%3}, {%4,%5,%6,%7}, {%8,%9}, {%0,%1,%2,%3};"
        : "+f"(c[0]), "+f"(c[1]), "+f"(c[2]), "+f"(c[3])
        : "r"(a[0]), "r"(a[1]), "r"(a[2]), "r"(a[3]), "r"(b0), "r"(b1));
}

// ---------- codebook conversion (tiny) ----------
__global__ void __launch_bounds__(256) vq_convE(const float* __restrict__ emb) {
    int k = blockIdx.x * 256 + threadIdx.x;
    if (blockIdx.x == 0 && threadIdx.x == 0) g_flag_count = 0;
    if (k >= K) return;
    const float4* er = reinterpret_cast<const float4*>(emb + (size_t)k * D);
    uint4* r1 = reinterpret_cast<uint4*>(g_B1 + (size_t)k * 128);
    uint4* r2 = reinterpret_cast<uint4*>(g_B2 + (size_t)k * 128);
    float s = 0.f;
#pragma unroll
    for (int i = 0; i < 8; i++) {
        float4 a = er[2 * i], b = er[2 * i + 1];
        float f[8] = {a.x, a.y, a.z, a.w, b.x, b.y, b.z, b.w};
        __nv_bfloat16 h[8], m[8];
#pragma unroll
        for (int e = 0; e < 8; e++) {
            s += f[e] * f[e];
            h[e] = __float2bfloat16_rn(f[e]);
            m[e] = __float2bfloat16_rn(f[e] - __bfloat162float(h[e]));
        }
        uint4 hv = *reinterpret_cast<uint4*>(h);
        uint4 mv = *reinterpret_cast<uint4*>(m);
        r1[i] = hv; r1[8 + i] = hv;      // [h | h]
        r2[i] = mv; r2[8 + i] = mv;      // [m | m]
    }
    g_enorm2[k] = s;
}

// load one B chunk (64 codewords, B1+B2) into stage
__device__ __forceinline__ void load_B(uint32_t sb, int chunk, int stage, int tid) {
    uint32_t base = sb + OFF_B + stage * 32768;
    const char* s1 = reinterpret_cast<const char*>(g_B1 + (size_t)chunk * NCHUNK * 128);
    const char* s2 = reinterpret_cast<const char*>(g_B2 + (size_t)chunk * NCHUNK * 128);
#pragma unroll
    for (int it = 0; it < 8; it++) {
        int i = tid + it * 256;                // 0..2047
        int mat = i >> 10;
        int rem = i & 1023;
        int row = rem >> 4, seg = rem & 15;
        const char* src = (mat ? s2 : s1) + row * 256 + seg * 16;
        cp16(base + mat * 16384 + row * 256 + ((seg ^ (row & 7)) << 4), src);
    }
}

#define UPD(dv, nn, B1v, I1v, B2v) \
    if ((dv) < (B1v)) { (B2v) = (B1v); (B1v) = (dv); (I1v) = (nn); } \
    else if ((dv) < (B2v)) { (B2v) = (dv); }

// ---------- mega kernel: convert-A + GEMM + argmin + finalize ----------
__global__ void __launch_bounds__(256, 2) vq_gemm(const float* __restrict__ x,
                                                  const float* __restrict__ emb,
                                                  float* __restrict__ out, int out_size) {
    extern __shared__ char sm[];
    uint32_t sb = smem_u32(sm);
    const int tid = threadIdx.x, wid = tid >> 5, l = tid & 31;

    // async prologue: e-norms + B chunks 0,1 (started first so they overlap A conv)
    cp16(sb + OFF_SN + tid * 16, reinterpret_cast<const char*>(g_enorm2) + tid * 16);
    load_B(sb, 0, 0, tid);
    cp_commit();                               // G0: sn + B0
    load_B(sb, 1, 1, tid);
    cp_commit();                               // G1: B1

    // A tile: load fp32 x, split to bf16 h|m, STS swizzled
    {
        const int row = tid >> 1, hf = tid & 1;
        const float4* xr = reinterpret_cast<const float4*>(
            x + ((size_t)(blockIdx.x * MTILE + row)) * D + hf * 32);
        uint4 hv[2], mv[2];
#pragma unroll
        for (int g = 0; g < 2; g++) {          // 2 groups of 16 floats
            __nv_bfloat162 hb[4], mb[4];
#pragma unroll
            for (int i = 0; i < 4; i++) {
                float4 f = xr[g * 4 + i];
                __nv_bfloat162 h0 = __float22bfloat162_rn(make_float2(f.x, f.y));
                __nv_bfloat162 h1 = __float22bfloat162_rn(make_float2(f.z, f.w));
                float2 h0f = __bfloat1622float2(h0), h1f = __bfloat1622float2(h1);
                __nv_bfloat162 m0 = __float22bfloat162_rn(make_float2(f.x - h0f.x, f.y - h0f.y));
                __nv_bfloat162 m1 = __float22bfloat162_rn(make_float2(f.z - h1f.x, f.w - h1f.y));
                hb[i] = (i & 1) ? h1 : h0;     // placeholder ordering fixed below
                // pack: two bf16x2 per float4 -> but we need [h0 h1] consecutive
                if (i == 0) { hb[0] = h0; hb[1] = h1; mb[0] = m0; mb[1] = m1; }
                else if (i == 1) { hb[2] = h0; hb[3] = h1; mb[2] = m0; mb[3] = m1; }
                else if (i == 2) { hv[g].x = *reinterpret_cast<uint32_t*>(&hb[0]);
                                   // handled after loop
                                   hb[0] = h0; hb[1] = h1; mb[0] = m0; mb[1] = m1; }
            }
            (void)hb; (void)mb;
            // recompute cleanly (simpler, compiler folds): build 8 bf16x2 per region
        }
        // --- simpler, explicit conversion path (overrides the above) ---
        uint32_t hseg[8], mseg[8];             // 32 bf16 each = 8 uint32 each? (16B x 4 segs -> 4 uint32/seg)
#pragma unroll
        for (int i = 0; i < 8; i++) {
            float4 f = xr[i];
            __nv_bfloat162 h0 = __float22bfloat162_rn(make_float2(f.x, f.y));
            __nv_bfloat162 h1 = __float22bfloat162_rn(make_float2(f.z, f.w));
            float2 h0f = __bfloat1622float2(h0), h1f = __bfloat1622float2(h1);
            __nv_bfloat162 m0 = __float22bfloat162_rn(make_float2(f.x - h0f.x, f.y - h0f.y));
            __nv_bfloat162 m1 = __float22bfloat162_rn(make_float2(f.z - h1f.x, f.w - h1f.y));
            hseg[i] = ((uint32_t)__bfloat16_as_ushort(__high2bfloat16(h0)) << 16) |
                      (uint32_t)__bfloat16_as_ushort(__low2bfloat16(h0));
            // store as [lo, hi] pairs: write via two u32s
            // h bf16x2 #2i   = h0, #2i+1 = h1  -> pack into arrays of u32
            hseg[i] = *reinterpret_cast<uint32_t*>(&h0);
            mseg[i] = *reinterpret_cast<uint32_t*>(&m0);
            // we need h1/m1 too: handled by pairing below
            uint32_t h1u = *reinterpret_cast<uint32_t*>(&h1);
            uint32_t m1u = *reinterpret_cast<uint32_t*>(&m1);
            // stage into smem directly per float4: 8B of h + 8B of m
            int jb = hf * 64 + i * 8;          // byte offset of these 4 dims in h region
            int segh = jb >> 4, offh = jb & 15;
            uint32_t addrh = sb + OFF_A + (row * 256) + ((segh ^ (row & 7)) << 4) + offh;
            asm volatile("st.shared.v2.b32 [%0], {%1, %2};" :: "r"(addrh), "r"(hseg[i]), "r"(h1u));
            int jbm = 128 + hf * 64 + i * 8;   // m region
            int segm = jbm >> 4, offm = jbm & 15;
            uint32_t addrm = sb + OFF_A + (row * 256) + ((segm ^ (row & 7)) << 4) + offm;
            asm volatile("st.shared.v2.b32 [%0], {%1, %2};" :: "r"(addrm), "r"(mseg[i]), "r"(m1u));
        }
    }

    cp_wait<1>();                              // sn + B0 resident
    __syncthreads();                           // A STS visible

    // hoist A fragments for all 8 k-steps
    uint32_t aF[8][4];
    {
        int row = (wid << 4) + (l & 15);
        uint32_t rb = sb + OFF_A + row * 256;
#pragma unroll
        for (int j = 0; j < 8; j++) {
            int seg = j * 2 + (l >> 4);
            ldsm4(aF[j], rb + ((seg ^ (row & 7)) << 4));
        }
    }
    const float* snp = reinterpret_cast<const float*>(sm + OFF_SN);

    float b1a = 3.4e38f, b2a = 3.4e38f, b1b = 3.4e38f, b2b = 3.4e38f;
    int i1a = 0, i1b = 0;

    for (int c = 0; c < NCHUNKS; c++) {
        if (c > 0) { cp_wait<1>(); __syncthreads(); }
        uint32_t stage = sb + OFF_B + (c & 1) * 32768;

        float C[8][4];
#pragma unroll
        for (int t = 0; t < 8; t++) { C[t][0] = C[t][1] = C[t][2] = C[t][3] = 0.f; }

#pragma unroll
        for (int mat = 0; mat < 2; mat++) {
            uint32_t bbase = stage + mat * 16384;
#pragma unroll
            for (int j = 0; j < 8; j++) {
#pragma unroll
                for (int g = 0; g < 4; g++) {
                    int row = (g << 4) + (l & 15);
                    int seg = j * 2 + (l >> 4);
                    uint32_t r[4];
                    ldsm4(r, bbase + row * 256 + ((seg ^ (row & 7)) << 4));
                    mma16816(C[2 * g],     aF[j], r[0], r[2]);
                    mma16816(C[2 * g + 1], aF[j], r[1], r[3]);
                }
            }
        }

#pragma unroll
        for (int t = 0; t < 8; t++) {
            int n0 = c * NCHUNK + t * 8 + 2 * (l & 3);
            float s0 = snp[n0], s1 = snp[n0 + 1];
            float d;
            d = fmaf(-2.f, C[t][0], s0); UPD(d, n0,     b1a, i1a, b2a);
            d = fmaf(-2.f, C[t][1], s1); UPD(d, n0 + 1, b1a, i1a, b2a);
            d = fmaf(-2.f, C[t][2], s0); UPD(d, n0,     b1b, i1b, b2b);
            d = fmaf(-2.f, C[t][3], s1); UPD(d, n0 + 1, b1b, i1b, b2b);
        }

        __syncthreads();
        if (c + 2 < NCHUNKS) load_B(sb, c + 2, c & 1, tid);
        cp_commit();
    }

    // cross-lane merge within 4-lane groups
#pragma unroll
    for (int off = 1; off <= 2; off <<= 1) {
        float p1 = __shfl_xor_sync(0xffffffffu, b1a, off);
        int   pi = __shfl_xor_sync(0xffffffffu, i1a, off);
        float p2 = __shfl_xor_sync(0xffffffffu, b2a, off);
        if (p1 < b1a || (p1 == b1a && pi < i1a)) { b2a = fminf(b1a, p2); b1a = p1; i1a = pi; }
        else                                      { b2a = fminf(b2a, p1); }
        p1 = __shfl_xor_sync(0xffffffffu, b1b, off);
        pi = __shfl_xor_sync(0xffffffffu, i1b, off);
        p2 = __shfl_xor_sync(0xffffffffu, b2b, off);
        if (p1 < b1b || (p1 == b1b && pi < i1b)) { b2b = fminf(b1b, p2); b1b = p1; i1b = pi; }
        else                                      { b2b = fminf(b2b, p1); }
    }

    int* sidx = reinterpret_cast<int*>(sm + OFF_IDX);
    int* sflg = reinterpret_cast<int*>(sm + OFF_FLG);
    if ((l & 3) == 0) {
        int r0 = wid * 16 + (l >> 2);
        int v = blockIdx.x * MTILE + r0;
        int fa = (b2a - b1a <= EPS), fb = (b2b - b1b <= EPS);
        sidx[r0] = i1a;  sflg[r0] = fa;
        sidx[r0 + 8] = i1b;  sflg[r0 + 8] = fb;
        if (fa) { int s = atomicAdd(&g_flag_count, 1); g_flag_list[s] = v; }
        if (fb) { int s = atomicAdd(&g_flag_count, 1); g_flag_list[s] = v + 8; }
    }
    __syncthreads();

    // fused finalize for non-flagged vectors (block-cooperative, coalesced)
    {
        const int r = tid >> 1, hf = tid & 1;
        const int v = blockIdx.x * MTILE + r;
        float lsum = 0.f;
        if (!sflg[r]) {
            int bi = sidx[r];
            const float4* er = reinterpret_cast<const float4*>(emb + (size_t)bi * D + hf * 32);
            const float4* xr = reinterpret_cast<const float4*>(x + (size_t)v * D + hf * 32);
            float4* o = reinterpret_cast<float4*>(out + (size_t)v * D + hf * 32);
#pragma unroll
            for (int i = 0; i < 8; i++) {
                float4 e = er[i]; float4 xx = xr[i];
                float dx = e.x - xx.x, dy = e.y - xx.y, dz = e.z - xx.z, dw = e.w - xx.w;
                lsum += dx * dx + dy * dy + dz * dz + dw * dw;
                float4 q;     // quantized = x + (e - x)
                q.x = xx.x + dx; q.y = xx.y + dy; q.z = xx.z + dz; q.w = xx.w + dw;
                o[i] = q;
            }
            if (hf == 0 && QELEMS + 1 + v < out_size) out[QELEMS + 1 + v] = (float)bi;
        }
#pragma unroll
        for (int off = 16; off > 0; off >>= 1)
            lsum += __shfl_down_sync(0xffffffffu, lsum, off);
        if (l == 0 && out_size > QELEMS)
            atomicAdd(out + QELEMS, lsum * (0.25f / (float)QELEMS));
    }
}

// ---------- exact rescan, warp-per-flagged-vector, full finalize ----------
__global__ void __launch_bounds__(256) vq_rescan(const float* __restrict__ x,
                                                 const float* __restrict__ emb,
                                                 float* __restrict__ out, int out_size) {
    __shared__ float sx[8][64];
    const int wid = threadIdx.x >> 5, lane = threadIdx.x & 31;
    int n = g_flag_count;
    if (n > NVEC) n = NVEC;
    for (int vi = blockIdx.x * 8 + wid; vi < n; vi += gridDim.x * 8) {
        int v = g_flag_list[vi];
        if (lane < 16)
            reinterpret_cast<float4*>(sx[wid])[lane] =
                reinterpret_cast<const float4*>(x + (size_t)v * D)[lane];
        __syncwarp();
        float best = 3.4e38f; int bi = K;
        const float* xs = sx[wid];
#pragma unroll 4
        for (int kk = 0; kk < 32; kk++) {
            int k = kk * 32 + lane;
            const float4* er = reinterpret_cast<const float4*>(emb + (size_t)k * D);
            float dot = 0.f;
#pragma unroll
            for (int i = 0; i < 16; i++) {
                float4 e = er[i];
                dot += xs[4*i] * e.x + xs[4*i+1] * e.y + xs[4*i+2] * e.z + xs[4*i+3] * e.w;
            }
            float d = fmaf(-2.f, dot, g_enorm2[k]);
            if (d < best || (d == best && k < bi)) { best = d; bi = k; }
        }
#pragma unroll
        for (int off = 16; off > 0; off >>= 1) {
            float ob = __shfl_xor_sync(0xffffffffu, best, off);
            int   oi = __shfl_xor_sync(0xffffffffu, bi, off);
            if (ob < best || (ob == best && oi < bi)) { best = ob; bi = oi; }
        }
        // full finalize for this vector
        float lsum = 0.f;
        if (lane < 16) {
            float4 e  = reinterpret_cast<const float4*>(emb + (size_t)bi * D)[lane];
            float4 xx = reinterpret_cast<const float4*>(x + (size_t)v * D)[lane];
            float dx = e.x - xx.x, dy = e.y - xx.y, dz = e.z - xx.z, dw = e.w - xx.w;
            lsum = dx * dx + dy * dy + dz * dz + dw * dw;
            float4 q;
            q.x = xx.x + dx; q.y = xx.y + dy; q.z = xx.z + dz; q.w = xx.w + dw;
            reinterpret_cast<float4*>(out + (size_t)v * D)[lane] = q;
        }
#pragma unroll
        for (int off = 16; off > 0; off >>= 1)
            lsum += __shfl_down_sync(0xffffffffu, lsum, off);
        if (lane == 0) {
            if (out_size > QELEMS)
                atomicAdd(out + QELEMS, lsum * (0.25f / (float)QELEMS));
            if (QELEMS + 1 + v < out_size) out[QELEMS + 1 + v] = (float)bi;
        }
        __syncwarp();
    }
}

extern "C" void kernel_launch(void* const* d_in, const int* in_sizes, int n_in,
                              void* d_out, int out_size) {
    const float* x   = (const float*)d_in[0];
    const float* emb = (const float*)d_in[1];
    if (n_in >= 2 && in_sizes[0] == K * D && in_sizes[1] == QELEMS) {
        const float* t = x; x = emb; emb = t;
    }
    float* out = (float*)d_out;

    if (out_size > QELEMS)
        cudaMemsetAsync(out + QELEMS, 0, sizeof(float), 0);

    cudaFuncSetAttribute(vq_gemm, cudaFuncAttributeMaxDynamicSharedMemorySize, SMEM_SZ);

    vq_convE<<<4, 256>>>(emb);
    vq_gemm<<<GRID, 256, SMEM_SZ>>>(x, emb, out, out_size);
    vq_rescan<<<128, 256>>>(x, emb, out, out_size);
}

// round 6
// speedup vs baseline: 1.1331x; 1.1331x over previous
#include <cuda_runtime.h>
#include <cuda_bf16.h>
#include <cstdint>

#define D        64
#define K        1024
#define NVEC     65536
#define QELEMS   (NVEC * D)
#define MTILE    128
#define NCHUNK   64
#define NCHUNKS  (K / NCHUNK)     // 16
#define GRID     (NVEC / MTILE)   // 512
#define EPS      0.02f

// smem offsets for GEMM kernel
#define OFF_A    0            // 128 rows x 256B (swizzled) = 32768
#define OFF_B    32768        // 2 stages x 24576 (B1 16K + B2 8K)
#define OFF_SN   81920        // 1024 floats = 4096
#define SMEM_SZ  86016

__device__ __nv_bfloat16 g_A [NVEC * 128];   // per vector: [h(64) | m(64)]
__device__ __nv_bfloat16 g_B1[K * 128];      // per codeword: [h | h]
__device__ __nv_bfloat16 g_B2[K * 64];       // per codeword: [m]
__device__ float g_enorm2[K];
__device__ int   g_bidx[NVEC];
__device__ int   g_flag_list[NVEC];
__device__ int   g_flag_count;

// ---------- helpers ----------
__device__ __forceinline__ uint32_t smem_u32(const void* p) {
    uint32_t a;
    asm("{ .reg .u64 t; cvta.to.shared.u64 t, %1; cvt.u32.u64 %0, t; }" : "=r"(a) : "l"(p));
    return a;
}
__device__ __forceinline__ void cp16(uint32_t dst, const void* src) {
    asm volatile("cp.async.cg.shared.global [%0], [%1], 16;" :: "r"(dst), "l"(src));
}
__device__ __forceinline__ void cp_commit() { asm volatile("cp.async.commit_group;" ::: "memory"); }
template<int N> __device__ __forceinline__ void cp_wait() {
    asm volatile("cp.async.wait_group %0;" :: "n"(N) : "memory");
}
__device__ __forceinline__ void ldsm4(uint32_t* r, uint32_t addr) {
    asm volatile("ldmatrix.sync.aligned.m8n8.x4.shared.b16 {%0,%1,%2,%3}, [%4];"
                 : "=r"(r[0]), "=r"(r[1]), "=r"(r[2]), "=r"(r[3]) : "r"(addr));
}
__device__ __forceinline__ void mma16816(float* c, const uint32_t* a, uint32_t b0, uint32_t b1) {
    asm volatile(
        "mma.sync.aligned.m16n8k16.row.col.f32.bf16.bf16.f32 "
        "{%0,%1,%2,%3}, {%4,%5,%6,%7}, {%8,%9}, {%0,%1,%2,%3};"
        : "+f"(c[0]), "+f"(c[1]), "+f"(c[2]), "+f"(c[3])
        : "r"(a[0]), "r"(a[1]), "r"(a[2]), "r"(a[3]), "r"(b0), "r"(b1));
}

// ---------- conversion: A, 2 threads/vector ----------
__global__ void __launch_bounds__(256) vq_convA(const float* __restrict__ x) {
    int t = blockIdx.x * 256 + threadIdx.x;     // 0 .. 2*NVEC-1
    int v = t >> 1, hf = t & 1;
    const float4* xr = reinterpret_cast<const float4*>(x + (size_t)v * D + hf * 32);
    uint4* oh = reinterpret_cast<uint4*>(g_A + (size_t)v * 128 + hf * 32);
    uint4* om = reinterpret_cast<uint4*>(g_A + (size_t)v * 128 + 64 + hf * 32);
#pragma unroll
    for (int i = 0; i < 4; i++) {               // 4 x (8 floats -> 16B h + 16B m)
        float4 a = xr[2 * i], b = xr[2 * i + 1];
        float f[8] = {a.x, a.y, a.z, a.w, b.x, b.y, b.z, b.w};
        __nv_bfloat16 h[8], m[8];
#pragma unroll
        for (int e = 0; e < 8; e++) {
            h[e] = __float2bfloat16_rn(f[e]);
            m[e] = __float2bfloat16_rn(f[e] - __bfloat162float(h[e]));
        }
        oh[i] = *reinterpret_cast<uint4*>(h);
        om[i] = *reinterpret_cast<uint4*>(m);
    }
}

// ---------- conversion: E, 8 threads/codeword ----------
__global__ void __launch_bounds__(256) vq_convE(const float* __restrict__ emb) {
    int t = blockIdx.x * 256 + threadIdx.x;     // 0 .. 8K-1
    if (t == 0) g_flag_count = 0;
    int k = t >> 3, j = t & 7;                  // j: which 8-dim slice
    const float4* er = reinterpret_cast<const float4*>(emb + (size_t)k * D + j * 8);
    float4 a = er[0], b = er[1];
    float f[8] = {a.x, a.y, a.z, a.w, b.x, b.y, b.z, b.w};
    __nv_bfloat16 h[8], m[8];
    float s = 0.f;
#pragma unroll
    for (int e = 0; e < 8; e++) {
        s += f[e] * f[e];
        h[e] = __float2bfloat16_rn(f[e]);
        m[e] = __float2bfloat16_rn(f[e] - __bfloat162float(h[e]));
    }
    uint4 hv = *reinterpret_cast<uint4*>(h);
    uint4 mv = *reinterpret_cast<uint4*>(m);
    uint4* r1 = reinterpret_cast<uint4*>(g_B1 + (size_t)k * 128 + j * 8);
    r1[0] = hv; r1[8] = hv;                     // [h | h] (dup at +64 elems = +8 uint4)
    *reinterpret_cast<uint4*>(g_B2 + (size_t)k * 64 + j * 8) = mv;
    // 8-lane reduction for ||e||^2
#pragma unroll
    for (int off = 4; off > 0; off >>= 1) s += __shfl_xor_sync(0xffffffffu, s, off);
    if (j == 0) g_enorm2[k] = s;
}

// load one B chunk: B1 (64 rows x 256B) + B2 (64 rows x 128B)
__device__ __forceinline__ void load_B(uint32_t sb, int chunk, int stage, int tid) {
    uint32_t base = sb + OFF_B + stage * 24576;
    const char* s1 = reinterpret_cast<const char*>(g_B1 + (size_t)chunk * NCHUNK * 128);
    const char* s2 = reinterpret_cast<const char*>(g_B2 + (size_t)chunk * NCHUNK * 64);
#pragma unroll
    for (int it = 0; it < 4; it++) {
        int i = tid + it * 256;                 // 0..1023
        int row = i >> 4, seg = i & 15;
        cp16(base + row * 256 + ((seg ^ (row & 7)) << 4), s1 + row * 256 + seg * 16);
    }
#pragma unroll
    for (int it = 0; it < 2; it++) {
        int i = tid + it * 256;                 // 0..511
        int row = i >> 3, seg = i & 7;
        cp16(base + 16384 + row * 128 + ((seg ^ (row & 7)) << 4), s2 + row * 128 + seg * 16);
    }
}

#define UPD(dv, nn, B1v, I1v, B2v) \
    if ((dv) < (B1v)) { (B2v) = (B1v); (B1v) = (dv); (I1v) = (nn); } \
    else if ((dv) < (B2v)) { (B2v) = (dv); }

// ---------- main GEMM + argmin kernel ----------
__global__ void __launch_bounds__(256, 2) vq_gemm() {
    extern __shared__ char sm[];
    uint32_t sb = smem_u32(sm);
    const int tid = threadIdx.x, wid = tid >> 5, l = tid & 31;

    // prologue: A tile + e-norms + B chunk 0 (G0); B chunk 1 (G1)
    {
        const char* asrc = reinterpret_cast<const char*>(g_A + (size_t)blockIdx.x * MTILE * 128);
#pragma unroll
        for (int it = 0; it < 8; it++) {
            int i = tid + it * 256;             // 0..2047
            int row = i >> 4, seg = i & 15;
            cp16(sb + OFF_A + row * 256 + ((seg ^ (row & 7)) << 4), asrc + row * 256 + seg * 16);
        }
        cp16(sb + OFF_SN + tid * 16, reinterpret_cast<const char*>(g_enorm2) + tid * 16);
        load_B(sb, 0, 0, tid);
        cp_commit();                            // G0
        load_B(sb, 1, 1, tid);
        cp_commit();                            // G1
    }
    cp_wait<1>();
    __syncthreads();

    // hoist A fragments for all 8 k-steps (j<4 = h half, j>=4 = m half)
    uint32_t aF[8][4];
    {
        int row = (wid << 4) + (l & 15);
        uint32_t rb = sb + OFF_A + row * 256;
#pragma unroll
        for (int j = 0; j < 8; j++) {
            int seg = j * 2 + (l >> 4);
            ldsm4(aF[j], rb + ((seg ^ (row & 7)) << 4));
        }
    }
    const float* snp = reinterpret_cast<const float*>(sm + OFF_SN);

    float b1a = 3.4e38f, b2a = 3.4e38f, b1b = 3.4e38f, b2b = 3.4e38f;
    int i1a = 0, i1b = 0;

    for (int c = 0; c < NCHUNKS; c++) {
        if (c > 0) { cp_wait<1>(); __syncthreads(); }
        uint32_t stage = sb + OFF_B + (c & 1) * 24576;

        float C[8][4];
#pragma unroll
        for (int t = 0; t < 8; t++) { C[t][0] = C[t][1] = C[t][2] = C[t][3] = 0.f; }

        // mat 0: [h|m] x [h|h]  (K=128, 8 k-steps)  -> h.h + m.h
#pragma unroll
        for (int j = 0; j < 8; j++) {
#pragma unroll
            for (int g = 0; g < 4; g++) {
                int row = (g << 4) + (l & 15);
                int seg = j * 2 + (l >> 4);
                uint32_t r[4];
                ldsm4(r, stage + row * 256 + ((seg ^ (row & 7)) << 4));
                mma16816(C[2 * g],     aF[j], r[0], r[2]);
                mma16816(C[2 * g + 1], aF[j], r[1], r[3]);
            }
        }
        // mat 1: h x [m]  (K=64, 4 k-steps) -> h.m   (m.m dropped; < EPS/2)
#pragma unroll
        for (int j = 0; j < 4; j++) {
#pragma unroll
            for (int g = 0; g < 4; g++) {
                int row = (g << 4) + (l & 15);
                int seg = j * 2 + (l >> 4);
                uint32_t r[4];
                ldsm4(r, stage + 16384 + row * 128 + ((seg ^ (row & 7)) << 4));
                mma16816(C[2 * g],     aF[j], r[0], r[2]);
                mma16816(C[2 * g + 1], aF[j], r[1], r[3]);
            }
        }

        // epilogue: d = ||e||^2 - 2*dot, two-min tracking
#pragma unroll
        for (int t = 0; t < 8; t++) {
            int n0 = c * NCHUNK + t * 8 + 2 * (l & 3);
            float s0 = snp[n0], s1 = snp[n0 + 1];
            float d;
            d = fmaf(-2.f, C[t][0], s0); UPD(d, n0,     b1a, i1a, b2a);
            d = fmaf(-2.f, C[t][1], s1); UPD(d, n0 + 1, b1a, i1a, b2a);
            d = fmaf(-2.f, C[t][2], s0); UPD(d, n0,     b1b, i1b, b2b);
            d = fmaf(-2.f, C[t][3], s1); UPD(d, n0 + 1, b1b, i1b, b2b);
        }

        __syncthreads();
        if (c + 2 < NCHUNKS) load_B(sb, c + 2, c & 1, tid);
        cp_commit();
    }

    // cross-lane merge within 4-lane groups (same rows, interleaved cols)
#pragma unroll
    for (int off = 1; off <= 2; off <<= 1) {
        float p1 = __shfl_xor_sync(0xffffffffu, b1a, off);
        int   pi = __shfl_xor_sync(0xffffffffu, i1a, off);
        float p2 = __shfl_xor_sync(0xffffffffu, b2a, off);
        if (p1 < b1a || (p1 == b1a && pi < i1a)) { b2a = fminf(b1a, p2); b1a = p1; i1a = pi; }
        else                                      { b2a = fminf(b2a, p1); }
        p1 = __shfl_xor_sync(0xffffffffu, b1b, off);
        pi = __shfl_xor_sync(0xffffffffu, i1b, off);
        p2 = __shfl_xor_sync(0xffffffffu, b2b, off);
        if (p1 < b1b || (p1 == b1b && pi < i1b)) { b2b = fminf(b1b, p2); b1b = p1; i1b = pi; }
        else                                      { b2b = fminf(b2b, p1); }
    }

    if ((l & 3) == 0) {
        int v = blockIdx.x * MTILE + wid * 16 + (l >> 2);
        g_bidx[v] = i1a;
        if (b2a - b1a <= EPS) { int s = atomicAdd(&g_flag_count, 1); g_flag_list[s] = v; }
        g_bidx[v + 8] = i1b;
        if (b2b - b1b <= EPS) { int s = atomicAdd(&g_flag_count, 1); g_flag_list[s] = v + 8; }
    }
}

// ---------- exact rescan, warp-per-flagged-vector ----------
__global__ void __launch_bounds__(256) vq_rescan(const float* __restrict__ x,
                                                 const float* __restrict__ emb) {
    __shared__ float sx[8][64];
    const int wid = threadIdx.x >> 5, lane = threadIdx.x & 31;
    int n = g_flag_count;
    if (n > NVEC) n = NVEC;
    for (int vi = blockIdx.x * 8 + wid; vi < n; vi += gridDim.x * 8) {
        int v = g_flag_list[vi];
        if (lane < 16)
            reinterpret_cast<float4*>(sx[wid])[lane] =
                reinterpret_cast<const float4*>(x + (size_t)v * D)[lane];
        __syncwarp();
        float best = 3.4e38f; int bi = K;
        const float* xs = sx[wid];
#pragma unroll 2
        for (int kk = 0; kk < 32; kk++) {
            int k = kk * 32 + lane;
            const float4* er = reinterpret_cast<const float4*>(emb + (size_t)k * D);
            float dot = 0.f;
#pragma unroll
            for (int i = 0; i < 16; i++) {
                float4 e = er[i];
                dot += xs[4*i] * e.x + xs[4*i+1] * e.y + xs[4*i+2] * e.z + xs[4*i+3] * e.w;
            }
            float d = fmaf(-2.f, dot, g_enorm2[k]);
            if (d < best) { best = d; bi = k; }     // lanes scan ascending k
        }
#pragma unroll
        for (int off = 16; off > 0; off >>= 1) {
            float ob = __shfl_xor_sync(0xffffffffu, best, off);
            int   oi = __shfl_xor_sync(0xffffffffu, bi, off);
            if (ob < best || (ob == best && oi < bi)) { best = ob; bi = oi; }
        }
        if (lane == 0) g_bidx[v] = bi;
        __syncwarp();
    }
}

// ---------- finalize: gather, quantized, loss, indices (2 threads/vector) ----------
__global__ void __launch_bounds__(256) vq_final(const float* __restrict__ x,
                                                const float* __restrict__ emb,
                                                float* __restrict__ out, int out_size) {
    const int t = blockIdx.x * 256 + threadIdx.x;
    const int v = t >> 1, hf = t & 1;
    int bi = g_bidx[v];
    float lsum = 0.f;
    {
        const float4* er = reinterpret_cast<const float4*>(emb + (size_t)bi * D + hf * 32);
        const float4* xr = reinterpret_cast<const float4*>(x + (size_t)v * D + hf * 32);
        float4* o = reinterpret_cast<float4*>(out + (size_t)v * D + hf * 32);
#pragma unroll
        for (int i = 0; i < 8; i++) {
            float4 e = er[i]; float4 xx = xr[i];
            float dx = e.x - xx.x, dy = e.y - xx.y, dz = e.z - xx.z, dw = e.w - xx.w;
            lsum += dx * dx + dy * dy + dz * dz + dw * dw;
            float4 q;   // quantized = x + (e - x), matching reference arithmetic
            q.x = xx.x + dx; q.y = xx.y + dy; q.z = xx.z + dz; q.w = xx.w + dw;
            o[i] = q;
        }
    }
#pragma unroll
    for (int off = 16; off > 0; off >>= 1)
        lsum += __shfl_down_sync(0xffffffffu, lsum, off);
    if ((threadIdx.x & 31) == 0 && out_size > QELEMS)
        atomicAdd(out + QELEMS, lsum * (0.25f / (float)QELEMS));
    if (hf == 0 && QELEMS + 1 + v < out_size) out[QELEMS + 1 + v] = (float)bi;
}

extern "C" void kernel_launch(void* const* d_in, const int* in_sizes, int n_in,
                              void* d_out, int out_size) {
    const float* x   = (const float*)d_in[0];
    const float* emb = (const float*)d_in[1];
    if (n_in >= 2 && in_sizes[0] == K * D && in_sizes[1] == QELEMS) {
        const float* t = x; x = emb; emb = t;
    }
    float* out = (float*)d_out;

    if (out_size > QELEMS)
        cudaMemsetAsync(out + QELEMS, 0, sizeof(float), 0);

    cudaFuncSetAttribute(vq_gemm, cudaFuncAttributeMaxDynamicSharedMemorySize, SMEM_SZ);

    vq_convA<<<NVEC * 2 / 256, 256>>>(x);
    vq_convE<<<K * 8 / 256, 256>>>(emb);
    vq_gemm<<<GRID, 256, SMEM_SZ>>>();
    vq_rescan<<<128, 256>>>(x, emb);
    vq_final<<<NVEC * 2 / 256, 256>>>(x, emb, out, out_size);
}

// round 7
// speedup vs baseline: 1.6747x; 1.4779x over previous
#include <cuda_runtime.h>
#include <cuda_bf16.h>
#include <cstdint>

#define D        64
#define K        1024
#define NVEC     65536
#define QELEMS   (NVEC * D)
#define MTILE    128
#define NCHUNK   64
#define NCHUNKS  (K / NCHUNK)     // 16
#define GRID     (NVEC / MTILE)   // 512
#define EPS      0.003f

// smem offsets for GEMM kernel
#define OFF_A    0            // 128 rows x 256B (swizzled) = 32768
#define OFF_B    32768        // 2 stages x 24576 (B1 16K + B2 8K)
#define OFF_SN   81920        // 1024 floats = 4096
#define SMEM_SZ  86016

__device__ __nv_bfloat16 g_A [NVEC * 128];   // per vector: [h(64) | m(64)]
__device__ __nv_bfloat16 g_B1[K * 128];      // per codeword: [h | h]
__device__ __nv_bfloat16 g_B2[K * 64];       // per codeword: [m]
__device__ float g_enorm2[K];
__device__ int   g_bidx[NVEC];
__device__ int   g_flag_list[NVEC];
__device__ int   g_flag_count;

// ---------- helpers ----------
__device__ __forceinline__ uint32_t smem_u32(const void* p) {
    uint32_t a;
    asm("{ .reg .u64 t; cvta.to.shared.u64 t, %1; cvt.u32.u64 %0, t; }" : "=r"(a) : "l"(p));
    return a;
}
__device__ __forceinline__ void cp16(uint32_t dst, const void* src) {
    asm volatile("cp.async.cg.shared.global [%0], [%1], 16;" :: "r"(dst), "l"(src));
}
__device__ __forceinline__ void cp_commit() { asm volatile("cp.async.commit_group;" ::: "memory"); }
template<int N> __device__ __forceinline__ void cp_wait() {
    asm volatile("cp.async.wait_group %0;" :: "n"(N) : "memory");
}
__device__ __forceinline__ void ldsm4(uint32_t* r, uint32_t addr) {
    asm volatile("ldmatrix.sync.aligned.m8n8.x4.shared.b16 {%0,%1,%2,%3}, [%4];"
                 : "=r"(r[0]), "=r"(r[1]), "=r"(r[2]), "=r"(r[3]) : "r"(addr));
}
__device__ __forceinline__ void mma16816(float* c, const uint32_t* a, uint32_t b0, uint32_t b1) {
    asm volatile(
        "mma.sync.aligned.m16n8k16.row.col.f32.bf16.bf16.f32 "
        "{%0,%1,%2,%3}, {%4,%5,%6,%7}, {%8,%9}, {%0,%1,%2,%3};"
        : "+f"(c[0]), "+f"(c[1]), "+f"(c[2]), "+f"(c[3])
        : "r"(a[0]), "r"(a[1]), "r"(a[2]), "r"(a[3]), "r"(b0), "r"(b1));
}

// ---------- combined conversion: blocks [0,512) convert A, [512,544) convert E ----------
#define ABLKS (NVEC * 2 / 256)    // 512
__global__ void __launch_bounds__(256) vq_conv(const float* __restrict__ x,
                                               const float* __restrict__ emb) {
    if (blockIdx.x < ABLKS) {
        int t = blockIdx.x * 256 + threadIdx.x;     // 0 .. 2*NVEC-1
        int v = t >> 1, hf = t & 1;
        const float4* xr = reinterpret_cast<const float4*>(x + (size_t)v * D + hf * 32);
        uint4* oh = reinterpret_cast<uint4*>(g_A + (size_t)v * 128 + hf * 32);
        uint4* om = reinterpret_cast<uint4*>(g_A + (size_t)v * 128 + 64 + hf * 32);
#pragma unroll
        for (int i = 0; i < 4; i++) {
            float4 a = xr[2 * i], b = xr[2 * i + 1];
            float f[8] = {a.x, a.y, a.z, a.w, b.x, b.y, b.z, b.w};
            __nv_bfloat16 h[8], m[8];
#pragma unroll
            for (int e = 0; e < 8; e++) {
                h[e] = __float2bfloat16_rn(f[e]);
                m[e] = __float2bfloat16_rn(f[e] - __bfloat162float(h[e]));
            }
            oh[i] = *reinterpret_cast<uint4*>(h);
            om[i] = *reinterpret_cast<uint4*>(m);
        }
    } else {
        int t = (blockIdx.x - ABLKS) * 256 + threadIdx.x;   // 0 .. 8K-1
        if (t == 0) g_flag_count = 0;
        int k = t >> 3, j = t & 7;
        const float4* er = reinterpret_cast<const float4*>(emb + (size_t)k * D + j * 8);
        float4 a = er[0], b = er[1];
        float f[8] = {a.x, a.y, a.z, a.w, b.x, b.y, b.z, b.w};
        __nv_bfloat16 h[8], m[8];
        float s = 0.f;
#pragma unroll
        for (int e = 0; e < 8; e++) {
            s += f[e] * f[e];
            h[e] = __float2bfloat16_rn(f[e]);
            m[e] = __float2bfloat16_rn(f[e] - __bfloat162float(h[e]));
        }
        uint4 hv = *reinterpret_cast<uint4*>(h);
        uint4 mv = *reinterpret_cast<uint4*>(m);
        uint4* r1 = reinterpret_cast<uint4*>(g_B1 + (size_t)k * 128 + j * 8);
        r1[0] = hv; r1[8] = hv;                     // [h | h]
        *reinterpret_cast<uint4*>(g_B2 + (size_t)k * 64 + j * 8) = mv;
#pragma unroll
        for (int off = 4; off > 0; off >>= 1) s += __shfl_xor_sync(0xffffffffu, s, off);
        if (j == 0) g_enorm2[k] = s;
    }
}

// load one B chunk: B1 (64 rows x 256B) + B2 (64 rows x 128B)
__device__ __forceinline__ void load_B(uint32_t sb, int chunk, int stage, int tid) {
    uint32_t base = sb + OFF_B + stage * 24576;
    const char* s1 = reinterpret_cast<const char*>(g_B1 + (size_t)chunk * NCHUNK * 128);
    const char* s2 = reinterpret_cast<const char*>(g_B2 + (size_t)chunk * NCHUNK * 64);
#pragma unroll
    for (int it = 0; it < 4; it++) {
        int i = tid + it * 256;
        int row = i >> 4, seg = i & 15;
        cp16(base + row * 256 + ((seg ^ (row & 7)) << 4), s1 + row * 256 + seg * 16);
    }
#pragma unroll
    for (int it = 0; it < 2; it++) {
        int i = tid + it * 256;
        int row = i >> 3, seg = i & 7;
        cp16(base + 16384 + row * 128 + ((seg ^ (row & 7)) << 4), s2 + row * 128 + seg * 16);
    }
}

#define UPD(dv, nn, B1v, I1v, B2v) \
    if ((dv) < (B1v)) { (B2v) = (B1v); (B1v) = (dv); (I1v) = (nn); } \
    else if ((dv) < (B2v)) { (B2v) = (dv); }

// ---------- main GEMM + argmin kernel ----------
__global__ void __launch_bounds__(256, 2) vq_gemm() {
    extern __shared__ char sm[];
    uint32_t sb = smem_u32(sm);
    const int tid = threadIdx.x, wid = tid >> 5, l = tid & 31;

    // prologue
    {
        const char* asrc = reinterpret_cast<const char*>(g_A + (size_t)blockIdx.x * MTILE * 128);
#pragma unroll
        for (int it = 0; it < 8; it++) {
            int i = tid + it * 256;
            int row = i >> 4, seg = i & 15;
            cp16(sb + OFF_A + row * 256 + ((seg ^ (row & 7)) << 4), asrc + row * 256 + seg * 16);
        }
        cp16(sb + OFF_SN + tid * 16, reinterpret_cast<const char*>(g_enorm2) + tid * 16);
        load_B(sb, 0, 0, tid);
        cp_commit();
        load_B(sb, 1, 1, tid);
        cp_commit();
    }
    cp_wait<1>();
    __syncthreads();

    uint32_t aF[8][4];
    {
        int row = (wid << 4) + (l & 15);
        uint32_t rb = sb + OFF_A + row * 256;
#pragma unroll
        for (int j = 0; j < 8; j++) {
            int seg = j * 2 + (l >> 4);
            ldsm4(aF[j], rb + ((seg ^ (row & 7)) << 4));
        }
    }
    const float* snp = reinterpret_cast<const float*>(sm + OFF_SN);

    float b1a = 3.4e38f, b2a = 3.4e38f, b1b = 3.4e38f, b2b = 3.4e38f;
    int i1a = 0, i1b = 0;

    for (int c = 0; c < NCHUNKS; c++) {
        if (c > 0) { cp_wait<1>(); __syncthreads(); }
        uint32_t stage = sb + OFF_B + (c & 1) * 24576;

        float C[8][4];
#pragma unroll
        for (int t = 0; t < 8; t++) { C[t][0] = C[t][1] = C[t][2] = C[t][3] = 0.f; }

        // [h|m] x [h|h]  (8 k-steps)
#pragma unroll
        for (int j = 0; j < 8; j++) {
#pragma unroll
            for (int g = 0; g < 4; g++) {
                int row = (g << 4) + (l & 15);
                int seg = j * 2 + (l >> 4);
                uint32_t r[4];
                ldsm4(r, stage + row * 256 + ((seg ^ (row & 7)) << 4));
                mma16816(C[2 * g],     aF[j], r[0], r[2]);
                mma16816(C[2 * g + 1], aF[j], r[1], r[3]);
            }
        }
        // h x [m]  (4 k-steps)
#pragma unroll
        for (int j = 0; j < 4; j++) {
#pragma unroll
            for (int g = 0; g < 4; g++) {
                int row = (g << 4) + (l & 15);
                int seg = j * 2 + (l >> 4);
                uint32_t r[4];
                ldsm4(r, stage + 16384 + row * 128 + ((seg ^ (row & 7)) << 4));
                mma16816(C[2 * g],     aF[j], r[0], r[2]);
                mma16816(C[2 * g + 1], aF[j], r[1], r[3]);
            }
        }

#pragma unroll
        for (int t = 0; t < 8; t++) {
            int n0 = c * NCHUNK + t * 8 + 2 * (l & 3);
            float s0 = snp[n0], s1 = snp[n0 + 1];
            float d;
            d = fmaf(-2.f, C[t][0], s0); UPD(d, n0,     b1a, i1a, b2a);
            d = fmaf(-2.f, C[t][1], s1); UPD(d, n0 + 1, b1a, i1a, b2a);
            d = fmaf(-2.f, C[t][2], s0); UPD(d, n0,     b1b, i1b, b2b);
            d = fmaf(-2.f, C[t][3], s1); UPD(d, n0 + 1, b1b, i1b, b2b);
        }

        __syncthreads();
        if (c + 2 < NCHUNKS) load_B(sb, c + 2, c & 1, tid);
        cp_commit();
    }

#pragma unroll
    for (int off = 1; off <= 2; off <<= 1) {
        float p1 = __shfl_xor_sync(0xffffffffu, b1a, off);
        int   pi = __shfl_xor_sync(0xffffffffu, i1a, off);
        float p2 = __shfl_xor_sync(0xffffffffu, b2a, off);
        if (p1 < b1a || (p1 == b1a && pi < i1a)) { b2a = fminf(b1a, p2); b1a = p1; i1a = pi; }
        else                                      { b2a = fminf(b2a, p1); }
        p1 = __shfl_xor_sync(0xffffffffu, b1b, off);
        pi = __shfl_xor_sync(0xffffffffu, i1b, off);
        p2 = __shfl_xor_sync(0xffffffffu, b2b, off);
        if (p1 < b1b || (p1 == b1b && pi < i1b)) { b2b = fminf(b1b, p2); b1b = p1; i1b = pi; }
        else                                      { b2b = fminf(b2b, p1); }
    }

    if ((l & 3) == 0) {
        int v = blockIdx.x * MTILE + wid * 16 + (l >> 2);
        g_bidx[v] = i1a;
        if (b2a - b1a <= EPS) { int s = atomicAdd(&g_flag_count, 1); g_flag_list[s] = v; }
        g_bidx[v + 8] = i1b;
        if (b2b - b1b <= EPS) { int s = atomicAdd(&g_flag_count, 1); g_flag_list[s] = v + 8; }
    }
}

// ---------- exact rescan: block-per-flagged-vector ----------
__global__ void __launch_bounds__(256) vq_rescan(const float* __restrict__ x,
                                                 const float* __restrict__ emb) {
    __shared__ float sx[64];
    __shared__ float sbest[256];
    __shared__ int   sidx[256];
    int n = g_flag_count;
    if (n > NVEC) n = NVEC;
    for (int vi = blockIdx.x; vi < n; vi += gridDim.x) {
        int v = g_flag_list[vi];
        __syncthreads();
        if (threadIdx.x < 16)
            reinterpret_cast<float4*>(sx)[threadIdx.x] =
                reinterpret_cast<const float4*>(x + (size_t)v * D)[threadIdx.x];
        __syncthreads();
        float best = 3.4e38f; int bi = K;
#pragma unroll
        for (int kk = 0; kk < 4; kk++) {
            int k = kk * 256 + threadIdx.x;
            const float4* er = reinterpret_cast<const float4*>(emb + (size_t)k * D);
            float dot = 0.f;
#pragma unroll
            for (int i = 0; i < 16; i++) {
                float4 e = er[i];
                dot += sx[4*i] * e.x + sx[4*i+1] * e.y + sx[4*i+2] * e.z + sx[4*i+3] * e.w;
            }
            float d = fmaf(-2.f, dot, g_enorm2[k]);
            if (d < best) { best = d; bi = k; }   // ascending k per thread
        }
        sbest[threadIdx.x] = best; sidx[threadIdx.x] = bi;
        __syncthreads();
        for (int s = 128; s > 0; s >>= 1) {
            if (threadIdx.x < s) {
                float ob = sbest[threadIdx.x + s]; int oi = sidx[threadIdx.x + s];
                if (ob < sbest[threadIdx.x] ||
                    (ob == sbest[threadIdx.x] && oi < sidx[threadIdx.x])) {
                    sbest[threadIdx.x] = ob; sidx[threadIdx.x] = oi;
                }
            }
            __syncthreads();
        }
        if (threadIdx.x == 0) g_bidx[v] = sidx[0];
    }
}

// ---------- finalize: gather, quantized, loss, indices (2 threads/vector) ----------
__global__ void __launch_bounds__(256) vq_final(const float* __restrict__ x,
                                                const float* __restrict__ emb,
                                                float* __restrict__ out, int out_size) {
    const int t = blockIdx.x * 256 + threadIdx.x;
    const int v = t >> 1, hf = t & 1;
    int bi = g_bidx[v];
    float lsum = 0.f;
    {
        const float4* er = reinterpret_cast<const float4*>(emb + (size_t)bi * D + hf * 32);
        const float4* xr = reinterpret_cast<const float4*>(x + (size_t)v * D + hf * 32);
        float4* o = reinterpret_cast<float4*>(out + (size_t)v * D + hf * 32);
#pragma unroll
        for (int i = 0; i < 8; i++) {
            float4 e = er[i]; float4 xx = xr[i];
            float dx = e.x - xx.x, dy = e.y - xx.y, dz = e.z - xx.z, dw = e.w - xx.w;
            lsum += dx * dx + dy * dy + dz * dz + dw * dw;
            float4 q;   // quantized = x + (e - x)
            q.x = xx.x + dx; q.y = xx.y + dy; q.z = xx.z + dz; q.w = xx.w + dw;
            o[i] = q;
        }
    }
#pragma unroll
    for (int off = 16; off > 0; off >>= 1)
        lsum += __shfl_down_sync(0xffffffffu, lsum, off);
    if ((threadIdx.x & 31) == 0 && out_size > QELEMS)
        atomicAdd(out + QELEMS, lsum * (0.25f / (float)QELEMS));
    if (hf == 0 && QELEMS + 1 + v < out_size) out[QELEMS + 1 + v] = (float)bi;
}

extern "C" void kernel_launch(void* const* d_in, const int* in_sizes, int n_in,
                              void* d_out, int out_size) {
    const float* x   = (const float*)d_in[0];
    const float* emb = (const float*)d_in[1];
    if (n_in >= 2 && in_sizes[0] == K * D && in_sizes[1] == QELEMS) {
        const float* t = x; x = emb; emb = t;
    }
    float* out = (float*)d_out;

    if (out_size > QELEMS)
        cudaMemsetAsync(out + QELEMS, 0, sizeof(float), 0);

    cudaFuncSetAttribute(vq_gemm, cudaFuncAttributeMaxDynamicSharedMemorySize, SMEM_SZ);

    vq_conv<<<ABLKS + K * 8 / 256, 256>>>(x, emb);
    vq_gemm<<<GRID, 256, SMEM_SZ>>>();
    vq_rescan<<<256, 256>>>(x, emb);
    vq_final<<<NVEC * 2 / 256, 256>>>(x, emb, out, out_size);
}

// round 8
// speedup vs baseline: 1.7215x; 1.0280x over previous
#include <cuda_runtime.h>
#include <cuda_bf16.h>
#include <cstdint>

#define D        64
#define K        1024
#define NVEC     65536
#define QELEMS   (NVEC * D)
#define MTILE    128
#define NCHUNK   64
#define NCHUNKS  (K / NCHUNK)     // 16
#define GRID     (NVEC / MTILE)   // 512
#define EPS      0.003f

// smem offsets for GEMM kernel
#define OFF_A    0            // 128 rows x 256B (swizzled) = 32768
#define OFF_B    32768        // 2 stages x 24576 (B1 16K + B2 8K)
#define OFF_SN   81920        // 1024 floats = 4096
#define OFF_IDX  86016        // 128 ints
#define OFF_FLG  86528        // 128 ints
#define OFF_RED  87040        // 8 floats (warp loss partials)
#define SMEM_SZ  87168

__device__ __nv_bfloat16 g_B1[K * 128];      // per codeword: [h | h]
__device__ __nv_bfloat16 g_B2[K * 64];       // per codeword: [m]
__device__ float g_enorm2[K];
__device__ int   g_flag_list[NVEC];
__device__ int   g_flag_count;

// ---------- helpers ----------
__device__ __forceinline__ uint32_t smem_u32(const void* p) {
    uint32_t a;
    asm("{ .reg .u64 t; cvta.to.shared.u64 t, %1; cvt.u32.u64 %0, t; }" : "=r"(a) : "l"(p));
    return a;
}
__device__ __forceinline__ void cp16(uint32_t dst, const void* src) {
    asm volatile("cp.async.cg.shared.global [%0], [%1], 16;" :: "r"(dst), "l"(src));
}
__device__ __forceinline__ void cp_commit() { asm volatile("cp.async.commit_group;" ::: "memory"); }
template<int N> __device__ __forceinline__ void cp_wait() {
    asm volatile("cp.async.wait_group %0;" :: "n"(N) : "memory");
}
__device__ __forceinline__ void ldsm4(uint32_t* r, uint32_t addr) {
    asm volatile("ldmatrix.sync.aligned.m8n8.x4.shared.b16 {%0,%1,%2,%3}, [%4];"
                 : "=r"(r[0]), "=r"(r[1]), "=r"(r[2]), "=r"(r[3]) : "r"(addr));
}
__device__ __forceinline__ void mma16816(float* c, const uint32_t* a, uint32_t b0, uint32_t b1) {
    asm volatile(
        "mma.sync.aligned.m16n8k16.row.col.f32.bf16.bf16.f32 "
        "{%0,%1,%2,%3}, {%4,%5,%6,%7}, {%8,%9}, {%0,%1,%2,%3};"
        : "+f"(c[0]), "+f"(c[1]), "+f"(c[2]), "+f"(c[3])
        : "r"(a[0]), "r"(a[1]), "r"(a[2]), "r"(a[3]), "r"(b0), "r"(b1));
}
__device__ __forceinline__ void sts16(uint32_t addr, uint4 v) {
    asm volatile("st.shared.v4.b32 [%0], {%1, %2, %3, %4};"
                 :: "r"(addr), "r"(v.x), "r"(v.y), "r"(v.z), "r"(v.w));
}

// ---------- codebook conversion ----------
__global__ void __launch_bounds__(256) vq_convE(const float* __restrict__ emb) {
    int t = blockIdx.x * 256 + threadIdx.x;     // 0 .. 8K-1
    if (t == 0) g_flag_count = 0;
    int k = t >> 3, j = t & 7;
    const float4* er = reinterpret_cast<const float4*>(emb + (size_t)k * D + j * 8);
    float4 a = er[0], b = er[1];
    float f[8] = {a.x, a.y, a.z, a.w, b.x, b.y, b.z, b.w};
    __nv_bfloat16 h[8], m[8];
    float s = 0.f;
#pragma unroll
    for (int e = 0; e < 8; e++) {
        s += f[e] * f[e];
        h[e] = __float2bfloat16_rn(f[e]);
        m[e] = __float2bfloat16_rn(f[e] - __bfloat162float(h[e]));
    }
    uint4 hv = *reinterpret_cast<uint4*>(h);
    uint4 mv = *reinterpret_cast<uint4*>(m);
    uint4* r1 = reinterpret_cast<uint4*>(g_B1 + (size_t)k * 128 + j * 8);
    r1[0] = hv; r1[8] = hv;                     // [h | h]
    *reinterpret_cast<uint4*>(g_B2 + (size_t)k * 64 + j * 8) = mv;
#pragma unroll
    for (int off = 4; off > 0; off >>= 1) s += __shfl_xor_sync(0xffffffffu, s, off);
    if (j == 0) g_enorm2[k] = s;
}

// load one B chunk: B1 (64 rows x 256B) + B2 (64 rows x 128B)
__device__ __forceinline__ void load_B(uint32_t sb, int chunk, int stage, int tid) {
    uint32_t base = sb + OFF_B + stage * 24576;
    const char* s1 = reinterpret_cast<const char*>(g_B1 + (size_t)chunk * NCHUNK * 128);
    const char* s2 = reinterpret_cast<const char*>(g_B2 + (size_t)chunk * NCHUNK * 64);
#pragma unroll
    for (int it = 0; it < 4; it++) {
        int i = tid + it * 256;
        int row = i >> 4, seg = i & 15;
        cp16(base + row * 256 + ((seg ^ (row & 7)) << 4), s1 + row * 256 + seg * 16);
    }
#pragma unroll
    for (int it = 0; it < 2; it++) {
        int i = tid + it * 256;
        int row = i >> 3, seg = i & 7;
        cp16(base + 16384 + row * 128 + ((seg ^ (row & 7)) << 4), s2 + row * 128 + seg * 16);
    }
}

#define UPD(dv, nn, B1v, I1v, B2v) \
    if ((dv) < (B1v)) { (B2v) = (B1v); (B1v) = (dv); (I1v) = (nn); } \
    else if ((dv) < (B2v)) { (B2v) = (dv); }

// ---------- mega kernel: A-convert + GEMM + argmin + finalize (non-flagged) ----------
__global__ void __launch_bounds__(256, 2) vq_gemm(const float* __restrict__ x,
                                                  const float* __restrict__ emb,
                                                  float* __restrict__ out, int out_size) {
    extern __shared__ char sm[];
    uint32_t sb = smem_u32(sm);
    const int tid = threadIdx.x, wid = tid >> 5, l = tid & 31;

    // start async loads first: e-norms + B0 (G0), B1 (G1)
    cp16(sb + OFF_SN + tid * 16, reinterpret_cast<const char*>(g_enorm2) + tid * 16);
    load_B(sb, 0, 0, tid);
    cp_commit();                                // G0
    load_B(sb, 1, 1, tid);
    cp_commit();                                // G1

    // A tile: load fp32 x (coalesced), split h/m in regs, STS swizzled
    {
        const int row = tid >> 1, hf = tid & 1;
        const float4* xr = reinterpret_cast<const float4*>(
            x + (size_t)(blockIdx.x * MTILE + row) * D + hf * 32);
        uint32_t abase = sb + OFF_A + row * 256;
#pragma unroll
        for (int i = 0; i < 4; i++) {           // 4 x (8 floats -> 16B h + 16B m)
            float4 a = xr[2 * i], b = xr[2 * i + 1];
            float f[8] = {a.x, a.y, a.z, a.w, b.x, b.y, b.z, b.w};
            __nv_bfloat16 h[8], m[8];
#pragma unroll
            for (int e = 0; e < 8; e++) {
                h[e] = __float2bfloat16_rn(f[e]);
                m[e] = __float2bfloat16_rn(f[e] - __bfloat162float(h[e]));
            }
            int segh = hf * 4 + i;              // h half: segs 0..7
            int segm = 8 + hf * 4 + i;          // m half: segs 8..15
            sts16(abase + ((segh ^ (row & 7)) << 4), *reinterpret_cast<uint4*>(h));
            sts16(abase + ((segm ^ (row & 7)) << 4), *reinterpret_cast<uint4*>(m));
        }
    }

    cp_wait<1>();                               // sn + B0 resident
    __syncthreads();                            // A STS visible

    // hoist A fragments (j<4 = h, j>=4 = m)
    uint32_t aF[8][4];
    {
        int row = (wid << 4) + (l & 15);
        uint32_t rb = sb + OFF_A + row * 256;
#pragma unroll
        for (int j = 0; j < 8; j++) {
            int seg = j * 2 + (l >> 4);
            ldsm4(aF[j], rb + ((seg ^ (row & 7)) << 4));
        }
    }
    const float* snp = reinterpret_cast<const float*>(sm + OFF_SN);

    float b1a = 3.4e38f, b2a = 3.4e38f, b1b = 3.4e38f, b2b = 3.4e38f;
    int i1a = 0, i1b = 0;

    for (int c = 0; c < NCHUNKS; c++) {
        if (c > 0) { cp_wait<1>(); __syncthreads(); }
        uint32_t stage = sb + OFF_B + (c & 1) * 24576;

        float C[8][4];
#pragma unroll
        for (int t = 0; t < 8; t++) { C[t][0] = C[t][1] = C[t][2] = C[t][3] = 0.f; }

        // [h|m] x [h|h] (8 k-steps)
#pragma unroll
        for (int j = 0; j < 8; j++) {
#pragma unroll
            for (int g = 0; g < 4; g++) {
                int row = (g << 4) + (l & 15);
                int seg = j * 2 + (l >> 4);
                uint32_t r[4];
                ldsm4(r, stage + row * 256 + ((seg ^ (row & 7)) << 4));
                mma16816(C[2 * g],     aF[j], r[0], r[2]);
                mma16816(C[2 * g + 1], aF[j], r[1], r[3]);
            }
        }
        // h x [m] (4 k-steps)
#pragma unroll
        for (int j = 0; j < 4; j++) {
#pragma unroll
            for (int g = 0; g < 4; g++) {
                int row = (g << 4) + (l & 15);
                int seg = j * 2 + (l >> 4);
                uint32_t r[4];
                ldsm4(r, stage + 16384 + row * 128 + ((seg ^ (row & 7)) << 4));
                mma16816(C[2 * g],     aF[j], r[0], r[2]);
                mma16816(C[2 * g + 1], aF[j], r[1], r[3]);
            }
        }

#pragma unroll
        for (int t = 0; t < 8; t++) {
            int n0 = c * NCHUNK + t * 8 + 2 * (l & 3);
            float s0 = snp[n0], s1 = snp[n0 + 1];
            float d;
            d = fmaf(-2.f, C[t][0], s0); UPD(d, n0,     b1a, i1a, b2a);
            d = fmaf(-2.f, C[t][1], s1); UPD(d, n0 + 1, b1a, i1a, b2a);
            d = fmaf(-2.f, C[t][2], s0); UPD(d, n0,     b1b, i1b, b2b);
            d = fmaf(-2.f, C[t][3], s1); UPD(d, n0 + 1, b1b, i1b, b2b);
        }

        __syncthreads();
        if (c + 2 < NCHUNKS) load_B(sb, c + 2, c & 1, tid);
        cp_commit();
    }

    // cross-lane merge within 4-lane groups
#pragma unroll
    for (int off = 1; off <= 2; off <<= 1) {
        float p1 = __shfl_xor_sync(0xffffffffu, b1a, off);
        int   pi = __shfl_xor_sync(0xffffffffu, i1a, off);
        float p2 = __shfl_xor_sync(0xffffffffu, b2a, off);
        if (p1 < b1a || (p1 == b1a && pi < i1a)) { b2a = fminf(b1a, p2); b1a = p1; i1a = pi; }
        else                                      { b2a = fminf(b2a, p1); }
        p1 = __shfl_xor_sync(0xffffffffu, b1b, off);
        pi = __shfl_xor_sync(0xffffffffu, i1b, off);
        p2 = __shfl_xor_sync(0xffffffffu, b2b, off);
        if (p1 < b1b || (p1 == b1b && pi < i1b)) { b2b = fminf(b1b, p2); b1b = p1; i1b = pi; }
        else                                      { b2b = fminf(b2b, p1); }
    }

    int* sidx = reinterpret_cast<int*>(sm + OFF_IDX);
    int* sflg = reinterpret_cast<int*>(sm + OFF_FLG);
    if ((l & 3) == 0) {
        int r0 = wid * 16 + (l >> 2);
        int v = blockIdx.x * MTILE + r0;
        int fa = (b2a - b1a <= EPS), fb = (b2b - b1b <= EPS);
        sidx[r0] = i1a;      sflg[r0] = fa;
        sidx[r0 + 8] = i1b;  sflg[r0 + 8] = fb;
        if (fa) { int s = atomicAdd(&g_flag_count, 1); g_flag_list[s] = v; }
        if (fb) { int s = atomicAdd(&g_flag_count, 1); g_flag_list[s] = v + 8; }
    }
    __syncthreads();

    // fused finalize for non-flagged vectors (2 threads/vector, coalesced)
    {
        const int r = tid >> 1, hf = tid & 1;
        const int v = blockIdx.x * MTILE + r;
        float lsum = 0.f;
        if (!sflg[r]) {
            int bi = sidx[r];
            const float4* er = reinterpret_cast<const float4*>(emb + (size_t)bi * D + hf * 32);
            const float4* xr = reinterpret_cast<const float4*>(x + (size_t)v * D + hf * 32);
            float4* o = reinterpret_cast<float4*>(out + (size_t)v * D + hf * 32);
#pragma unroll
            for (int i = 0; i < 8; i++) {
                float4 e = er[i]; float4 xx = xr[i];
                float dx = e.x - xx.x, dy = e.y - xx.y, dz = e.z - xx.z, dw = e.w - xx.w;
                lsum += dx * dx + dy * dy + dz * dz + dw * dw;
                float4 q;   // quantized = x + (e - x)
                q.x = xx.x + dx; q.y = xx.y + dy; q.z = xx.z + dz; q.w = xx.w + dw;
                o[i] = q;
            }
            if (hf == 0 && QELEMS + 1 + v < out_size) out[QELEMS + 1 + v] = (float)bi;
        }
        // block loss reduction -> 1 atomic per CTA
#pragma unroll
        for (int off = 16; off > 0; off >>= 1)
            lsum += __shfl_down_sync(0xffffffffu, lsum, off);
        float* sred = reinterpret_cast<float*>(sm + OFF_RED);
        if (l == 0) sred[wid] = lsum;
        __syncthreads();
        if (wid == 0) {
            float s = (l < 8) ? sred[l] : 0.f;
#pragma unroll
            for (int off = 4; off > 0; off >>= 1)
                s += __shfl_down_sync(0xffffffffu, s, off);
            if (l == 0 && out_size > QELEMS)
                atomicAdd(out + QELEMS, s * (0.25f / (float)QELEMS));
        }
    }
}

// ---------- exact rescan + full finalize for flagged vectors ----------
__global__ void __launch_bounds__(256) vq_rescan(const float* __restrict__ x,
                                                 const float* __restrict__ emb,
                                                 float* __restrict__ out, int out_size) {
    __shared__ float sx[64];
    __shared__ float sbest[256];
    __shared__ int   sidx[256];
    int n = g_flag_count;
    if (n > NVEC) n = NVEC;
    for (int vi = blockIdx.x; vi < n; vi += gridDim.x) {
        int v = g_flag_list[vi];
        __syncthreads();
        if (threadIdx.x < 16)
            reinterpret_cast<float4*>(sx)[threadIdx.x] =
                reinterpret_cast<const float4*>(x + (size_t)v * D)[threadIdx.x];
        __syncthreads();
        float best = 3.4e38f; int bi = K;
#pragma unroll
        for (int kk = 0; kk < 4; kk++) {
            int k = kk * 256 + threadIdx.x;
            const float4* er = reinterpret_cast<const float4*>(emb + (size_t)k * D);
            float dot = 0.f;
#pragma unroll
            for (int i = 0; i < 16; i++) {
                float4 e = er[i];
                dot += sx[4*i] * e.x + sx[4*i+1] * e.y + sx[4*i+2] * e.z + sx[4*i+3] * e.w;
            }
            float d = fmaf(-2.f, dot, g_enorm2[k]);
            if (d < best) { best = d; bi = k; }   // ascending k per thread
        }
        sbest[threadIdx.x] = best; sidx[threadIdx.x] = bi;
        __syncthreads();
        for (int s = 128; s > 0; s >>= 1) {
            if (threadIdx.x < s) {
                float ob = sbest[threadIdx.x + s]; int oi = sidx[threadIdx.x + s];
                if (ob < sbest[threadIdx.x] ||
                    (ob == sbest[threadIdx.x] && oi < sidx[threadIdx.x])) {
                    sbest[threadIdx.x] = ob; sidx[threadIdx.x] = oi;
                }
            }
            __syncthreads();
        }
        // full finalize for this vector (threads 0..15)
        int bfin = sidx[0];
        float lsum = 0.f;
        if (threadIdx.x < 16) {
            float4 e  = reinterpret_cast<const float4*>(emb + (size_t)bfin * D)[threadIdx.x];
            float4 xx = reinterpret_cast<const float4*>(x + (size_t)v * D)[threadIdx.x];
            float dx = e.x - xx.x, dy = e.y - xx.y, dz = e.z - xx.z, dw = e.w - xx.w;
            lsum = dx * dx + dy * dy + dz * dz + dw * dw;
            float4 q;
            q.x = xx.x + dx; q.y = xx.y + dy; q.z = xx.z + dz; q.w = xx.w + dw;
            reinterpret_cast<float4*>(out + (size_t)v * D)[threadIdx.x] = q;
        }
        if (threadIdx.x < 32) {
#pragma unroll
            for (int off = 8; off > 0; off >>= 1)
                lsum += __shfl_down_sync(0xffffffffu, lsum, off);
            if (threadIdx.x == 0) {
                if (out_size > QELEMS)
                    atomicAdd(out + QELEMS, lsum * (0.25f / (float)QELEMS));
                if (QELEMS + 1 + v < out_size) out[QELEMS + 1 + v] = (float)bfin;
            }
        }
    }
}

extern "C" void kernel_launch(void* const* d_in, const int* in_sizes, int n_in,
                              void* d_out, int out_size) {
    const float* x   = (const float*)d_in[0];
    const float* emb = (const float*)d_in[1];
    if (n_in >= 2 && in_sizes[0] == K * D && in_sizes[1] == QELEMS) {
        const float* t = x; x = emb; emb = t;
    }
    float* out = (float*)d_out;

    if (out_size > QELEMS)
        cudaMemsetAsync(out + QELEMS, 0, sizeof(float), 0);

    cudaFuncSetAttribute(vq_gemm, cudaFuncAttributeMaxDynamicSharedMemorySize, SMEM_SZ);

    vq_convE<<<K * 8 / 256, 256>>>(emb);
    vq_gemm<<<GRID, 256, SMEM_SZ>>>(x, emb, out, out_size);
    vq_rescan<<<256, 256>>>(x, emb, out, out_size);
}